// round 14
// baseline (speedup 1.0000x reference)
#include <cuda_runtime.h>
#include <cstdint>

// Problem constants (fixed by setup_inputs):
//   B=16, H_out=W_out=512 -> N = 262144 = 2^18
//   source: [B, 640, 640, 3] f32  (1228800 floats = 153600 32B-units per image)
//   idx:    [B, 2, N] f32
//   out:    [B, 512, 512, 3] f32
#define B_     16
#define N_     262144      // 2^18
#define N_LOG2 18
#define HS_    640
#define WS_    640
#define C_     3
#define PIX_PER_THREAD 4

struct f8 { float a0,a1,a2,a3,a4,a5,a6,a7; };

// Predicated 32B (256-bit, sm_100+) read-only load, write-only destinations.
// Off-lanes produce no transaction and leave garbage (discarded downstream).
__device__ __forceinline__ void ldg256_pred(f8& q, const float* p, int pred)
{
    asm("{\n\t"
        ".reg .pred %%pq;\n\t"
        "setp.ne.b32 %%pq, %8, 0;\n\t"
        "@%%pq ld.global.nc.v8.f32 {%0,%1,%2,%3,%4,%5,%6,%7}, [%9];\n\t"
        "}"
        : "=f"(q.a0), "=f"(q.a1), "=f"(q.a2), "=f"(q.a3),
          "=f"(q.a4), "=f"(q.a5), "=f"(q.a6), "=f"(q.a7)
        : "r"(pred), "l"(p));
}

__device__ __forceinline__ void ldg64_pred(float2& q, const float* p, int pred)
{
    asm("{\n\t"
        ".reg .pred %%pq;\n\t"
        "setp.ne.b32 %%pq, %2, 0;\n\t"
        "@%%pq ld.global.nc.v2.f32 {%0,%1}, [%3];\n\t"
        "}"
        : "=f"(q.x), "=f"(q.y)
        : "r"(pred), "l"(p));
}

// NOTE: no min-blocks clause — R12 proved capping registers serializes the
// batched loads (MLP collapse). Free allocation @ ~42% occ is the fast point.
__global__ __launch_bounds__(256)
void nn_gather_kernel(const float* __restrict__ idx,
                      const float* __restrict__ src,
                      float* __restrict__ out)
{
    const int64_t tid = (int64_t)blockIdx.x * blockDim.x + threadIdx.x;
    const int64_t p0  = tid * PIX_PER_THREAD;          // global pixel index
    const int     b   = (int)(p0 >> N_LOG2);
    const int     n   = (int)(p0 & (N_ - 1));          // multiple of 4 -> 16B aligned

    const float* idx_b = idx + (int64_t)b * 2 * N_;
    const float4 rv = *reinterpret_cast<const float4*>(idx_b + n);        // rows
    const float4 cv = *reinterpret_cast<const float4*>(idx_b + N_ + n);   // cols

    const float* src_b = src + (int64_t)b * (HS_ * WS_ * C_);   // 32B aligned

    const float rr[4] = {rv.x, rv.y, rv.z, rv.w};
    const float cc[4] = {cv.x, cv.y, cv.z, cv.w};

    // ---- phase 1: addresses + predicates for all 4 pixels ----
    // 32B units: straddle only when (off & 7) >= 6  -> 25% of pixels
    // => gather wavefronts 1.25 per valid pixel.
    int base8[4], rem[4], pv[4], pv2[4];
    #pragma unroll
    for (int k = 0; k < 4; ++k) {
        // trunc(x + 0.5) toward zero == __float2int_rz(x + 0.5f)
        const int ir = __float2int_rz(rr[k] + 0.5f);
        const int ic = __float2int_rz(cc[k] + 0.5f);
        const int valid = ((unsigned)ir < (unsigned)HS_) &
                          ((unsigned)ic < (unsigned)WS_);
        // clamp keeps the (dead) predicated-off address in-range
        const int irc = min(max(ir, 0), HS_ - 1);
        const int icc = min(max(ic, 0), WS_ - 1);
        const int off = (irc * WS_ + icc) * C_;   // float offset, multiple of 3
        base8[k] = off >> 3;                      // 32B unit index
        rem[k]   = off & 7;                       // 0..7
        pv[k]    = valid;
        pv2[k]   = valid & (rem[k] >= 6);         // straddles 32B boundary
    }

    // ---- phase 2: 4 v8 + 4 predicated v2 loads, front-batched (MLP ~8) ----
    f8     q0[4];
    float2 q1[4];
    #pragma unroll
    for (int k = 0; k < 4; ++k)
        ldg256_pred(q0[k], src_b + ((int64_t)base8[k] << 3), pv[k]);
    #pragma unroll
    for (int k = 0; k < 4; ++k)
        ldg64_pred(q1[k], src_b + (((int64_t)base8[k] + 1) << 3), pv2[k]);

    // ---- phase 3: barrel-shift extraction (13 SELs/pixel vs 21 for trees) ----
    // y[j] = data[rem + j], data = [a0..a7, x.x, x.y]. Log-shift by rem's bits.
    // Garbage-safety: predicated-off loads leave garbage, but pv=0 forces the
    // final outputs to 0, and rem<6 never routes x.x/x.y into y. SELs are
    // bitwise -> NaN-safe.
    float o[12];
    #pragma unroll
    for (int k = 0; k < 4; ++k) {
        const f8&    q = q0[k];
        const float2 x = q1[k];
        const bool s4 = (rem[k] & 4) != 0;
        const bool s2 = (rem[k] & 2) != 0;
        const bool s1 = (rem[k] & 1) != 0;

        // stage A: shift by 4 (6 SELs)
        const float t0 = s4 ? q.a4 : q.a0;
        const float t1 = s4 ? q.a5 : q.a1;
        const float t2 = s4 ? q.a6 : q.a2;
        const float t3 = s4 ? q.a7 : q.a3;
        const float t4 = s4 ? x.x  : q.a4;
        const float t5 = s4 ? x.y  : q.a5;
        // stage B: shift by 2 (4 SELs)
        const float u0 = s2 ? t2 : t0;
        const float u1 = s2 ? t3 : t1;
        const float u2 = s2 ? t4 : t2;
        const float u3 = s2 ? t5 : t3;
        // stage C: shift by 1 (3 SELs)
        const float y0 = s1 ? u1 : u0;
        const float y1 = s1 ? u2 : u1;
        const float y2 = s1 ? u3 : u2;

        o[3*k + 0] = pv[k] ? y0 : 0.0f;
        o[3*k + 1] = pv[k] ? y1 : 0.0f;
        o[3*k + 2] = pv[k] ? y2 : 0.0f;
    }

    // 4 pixels * 3ch = 12 floats = 48B at byte offset 48*tid -> 16B aligned
    float4* op = reinterpret_cast<float4*>(out + p0 * C_);
    op[0] = make_float4(o[0], o[1],  o[2],  o[3]);
    op[1] = make_float4(o[4], o[5],  o[6],  o[7]);
    op[2] = make_float4(o[8], o[9],  o[10], o[11]);
}

extern "C" void kernel_launch(void* const* d_in, const int* in_sizes, int n_in,
                              void* d_out, int out_size)
{
    const float* idx = (const float*)d_in[0];   // [B, 2, N] f32
    const float* src = (const float*)d_in[1];   // [B, 640, 640, 3] f32
    float* out = (float*)d_out;                 // [B, 512, 512, 3] f32

    const int64_t total_pixels  = (int64_t)B_ * N_;                 // 4,194,304
    const int64_t total_threads = total_pixels / PIX_PER_THREAD;    // 1,048,576
    const int threads = 256;
    const int blocks  = (int)(total_threads / threads);             // 4096

    nn_gather_kernel<<<blocks, threads>>>(idx, src, out);
}

// round 15
// speedup vs baseline: 1.0548x; 1.0548x over previous
#include <cuda_runtime.h>
#include <cstdint>

// Problem constants (fixed by setup_inputs):
//   B=16, H_out=W_out=512 -> N = 262144 = 2^18
//   source: [B, 640, 640, 3] f32  (1228800 floats = 153600 32B-units per image)
//   idx:    [B, 2, N] f32
//   out:    [B, 512, 512, 3] f32
#define B_     16
#define N_     262144      // 2^18
#define N_LOG2 18
#define HS_    640
#define WS_    640
#define C_     3
#define PIX_PER_THREAD 4
#define THREADS_PER_CTA 128   // finer CTA granularity: halves CTA duration ->
                              // halves tail-drain loss; 1 warp per SMSP

struct f8 { float a0,a1,a2,a3,a4,a5,a6,a7; };

// Predicated 32B (256-bit, sm_100+) read-only load, write-only destinations.
// Off-lanes produce no transaction and leave garbage (discarded downstream).
__device__ __forceinline__ void ldg256_pred(f8& q, const float* p, int pred)
{
    asm("{\n\t"
        ".reg .pred %%pq;\n\t"
        "setp.ne.b32 %%pq, %8, 0;\n\t"
        "@%%pq ld.global.nc.v8.f32 {%0,%1,%2,%3,%4,%5,%6,%7}, [%9];\n\t"
        "}"
        : "=f"(q.a0), "=f"(q.a1), "=f"(q.a2), "=f"(q.a3),
          "=f"(q.a4), "=f"(q.a5), "=f"(q.a6), "=f"(q.a7)
        : "r"(pred), "l"(p));
}

__device__ __forceinline__ void ldg64_pred(float2& q, const float* p, int pred)
{
    asm("{\n\t"
        ".reg .pred %%pq;\n\t"
        "setp.ne.b32 %%pq, %2, 0;\n\t"
        "@%%pq ld.global.nc.v2.f32 {%0,%1}, [%3];\n\t"
        "}"
        : "=f"(q.x), "=f"(q.y)
        : "r"(pred), "l"(p));
}

// NOTE: no min-blocks clause — R12 proved capping registers serializes the
// batched loads (MLP collapse). Free allocation is the fast point.
__global__ __launch_bounds__(THREADS_PER_CTA)
void nn_gather_kernel(const float* __restrict__ idx,
                      const float* __restrict__ src,
                      float* __restrict__ out)
{
    const int64_t tid = (int64_t)blockIdx.x * blockDim.x + threadIdx.x;
    const int64_t p0  = tid * PIX_PER_THREAD;          // global pixel index
    const int     b   = (int)(p0 >> N_LOG2);
    const int     n   = (int)(p0 & (N_ - 1));          // multiple of 4 -> 16B aligned

    const float* idx_b = idx + (int64_t)b * 2 * N_;
    const float4 rv = *reinterpret_cast<const float4*>(idx_b + n);        // rows
    const float4 cv = *reinterpret_cast<const float4*>(idx_b + N_ + n);   // cols

    const float* src_b = src + (int64_t)b * (HS_ * WS_ * C_);   // 32B aligned

    const float rr[4] = {rv.x, rv.y, rv.z, rv.w};
    const float cc[4] = {cv.x, cv.y, cv.z, cv.w};

    // ---- phase 1: addresses + predicates for all 4 pixels ----
    // 32B units: straddle only when (off & 7) >= 6  -> 25% of pixels
    // => gather wavefronts 1.25 per valid pixel.
    int base8[4], rem[4], pv[4], pv2[4];
    #pragma unroll
    for (int k = 0; k < 4; ++k) {
        // trunc(x + 0.5) toward zero == __float2int_rz(x + 0.5f)
        const int ir = __float2int_rz(rr[k] + 0.5f);
        const int ic = __float2int_rz(cc[k] + 0.5f);
        const int valid = ((unsigned)ir < (unsigned)HS_) &
                          ((unsigned)ic < (unsigned)WS_);
        // clamp keeps the (dead) predicated-off address in-range
        const int irc = min(max(ir, 0), HS_ - 1);
        const int icc = min(max(ic, 0), WS_ - 1);
        const int off = (irc * WS_ + icc) * C_;   // float offset, multiple of 3
        base8[k] = off >> 3;                      // 32B unit index
        rem[k]   = off & 7;                       // 0..7
        pv[k]    = valid;
        pv2[k]   = valid & (rem[k] >= 6);         // straddles 32B boundary
    }

    // ---- phase 2: 4 v8 + 4 predicated v2 loads, front-batched (MLP ~8) ----
    f8     q0[4];
    float2 q1[4];
    #pragma unroll
    for (int k = 0; k < 4; ++k)
        ldg256_pred(q0[k], src_b + ((int64_t)base8[k] << 3), pv[k]);
    #pragma unroll
    for (int k = 0; k < 4; ++k)
        ldg64_pred(q1[k], src_b + (((int64_t)base8[k] + 1) << 3), pv2[k]);

    // ---- phase 3: barrel-shift extraction (13 SELs/pixel) ----
    // y[j] = data[rem + j], data = [a0..a7, x.x, x.y]. Log-shift by rem's bits.
    // Garbage-safety: predicated-off loads leave garbage, but pv=0 forces the
    // final outputs to 0, and rem<6 never routes x.x/x.y into y. SELs are
    // bitwise -> NaN-safe.
    float o[12];
    #pragma unroll
    for (int k = 0; k < 4; ++k) {
        const f8&    q = q0[k];
        const float2 x = q1[k];
        const bool s4 = (rem[k] & 4) != 0;
        const bool s2 = (rem[k] & 2) != 0;
        const bool s1 = (rem[k] & 1) != 0;

        // stage A: shift by 4 (6 SELs)
        const float t0 = s4 ? q.a4 : q.a0;
        const float t1 = s4 ? q.a5 : q.a1;
        const float t2 = s4 ? q.a6 : q.a2;
        const float t3 = s4 ? q.a7 : q.a3;
        const float t4 = s4 ? x.x  : q.a4;
        const float t5 = s4 ? x.y  : q.a5;
        // stage B: shift by 2 (4 SELs)
        const float u0 = s2 ? t2 : t0;
        const float u1 = s2 ? t3 : t1;
        const float u2 = s2 ? t4 : t2;
        const float u3 = s2 ? t5 : t3;
        // stage C: shift by 1 (3 SELs)
        const float y0 = s1 ? u1 : u0;
        const float y1 = s1 ? u2 : u1;
        const float y2 = s1 ? u3 : u2;

        o[3*k + 0] = pv[k] ? y0 : 0.0f;
        o[3*k + 1] = pv[k] ? y1 : 0.0f;
        o[3*k + 2] = pv[k] ? y2 : 0.0f;
    }

    // 4 pixels * 3ch = 12 floats = 48B at byte offset 48*tid -> 16B aligned
    float4* op = reinterpret_cast<float4*>(out + p0 * C_);
    op[0] = make_float4(o[0], o[1],  o[2],  o[3]);
    op[1] = make_float4(o[4], o[5],  o[6],  o[7]);
    op[2] = make_float4(o[8], o[9],  o[10], o[11]);
}

extern "C" void kernel_launch(void* const* d_in, const int* in_sizes, int n_in,
                              void* d_out, int out_size)
{
    const float* idx = (const float*)d_in[0];   // [B, 2, N] f32
    const float* src = (const float*)d_in[1];   // [B, 640, 640, 3] f32
    float* out = (float*)d_out;                 // [B, 512, 512, 3] f32

    const int64_t total_pixels  = (int64_t)B_ * N_;                 // 4,194,304
    const int64_t total_threads = total_pixels / PIX_PER_THREAD;    // 1,048,576
    const int blocks = (int)(total_threads / THREADS_PER_CTA);      // 8192

    nn_gather_kernel<<<blocks, THREADS_PER_CTA>>>(idx, src, out);
}